// round 14
// baseline (speedup 1.0000x reference)
#include <cuda_runtime.h>
#include <math_constants.h>

#define N 384
#define D 128
#define MARGIN 0.2f
#define RHO 10.0f
#define NBLK_T N              // one block per anchor (best measured shape)
#define NWARP 8               // 256 threads

__device__ float  g_dist[N * N];
__device__ double g_num;
__device__ int    g_den;
__device__ int    g_count;    // zero-init; last block resets each replay

// ---------------------------------------------------------------------------
// Kernel A: pairwise squared distances, tiled 32x32 Gram, norms from smem.
// grid (12,12) = 144 blocks (one wave), 256 threads.
// ---------------------------------------------------------------------------
__global__ void __launch_bounds__(256)
dist_kernel(const float* __restrict__ emb) {
    __shared__ float As[32][D];
    __shared__ float Bs[D][33];
    __shared__ float sqA[32], sqB[32];

    const int bi = blockIdx.y * 32;
    const int bj = blockIdx.x * 32;
    const int tid = threadIdx.x;

    for (int idx = tid; idx < 32 * D; idx += 256) {
        int r = idx >> 7;
        int c = idx & (D - 1);
        As[r][c] = emb[(bi + r) * D + c];
        Bs[c][r] = emb[(bj + r) * D + c];
    }
    __syncthreads();

    if (tid < 32) {
        float s = 0.f;
#pragma unroll
        for (int d = 0; d < D; d++) s = fmaf(As[tid][d], As[tid][d], s);
        sqA[tid] = s;
    } else if (tid < 64) {
        const int r = tid - 32;
        float s = 0.f;
#pragma unroll
        for (int d = 0; d < D; d++) s = fmaf(Bs[d][r], Bs[d][r], s);
        sqB[r] = s;
    }
    __syncthreads();

    const int c  = tid & 31;
    const int r0 = tid >> 5;
    float acc[4] = {0.f, 0.f, 0.f, 0.f};
    for (int d = 0; d < D; d++) {
        float b = Bs[d][c];
#pragma unroll
        for (int q = 0; q < 4; q++)
            acc[q] = fmaf(As[r0 + 8 * q][d], b, acc[q]);
    }
#pragma unroll
    for (int q = 0; q < 4; q++) {
        const int r = r0 + 8 * q;
        float dist = sqA[r] + sqB[c] - 2.0f * acc[q];
        g_dist[(bi + r) * N + (bj + c)] = fmaxf(dist, 0.0f);
    }
}

// ---------------------------------------------------------------------------
// Kernel B: per-anchor triplet reduction (384 blocks, 256 thr) + finalize.
// Ballot-compacted positive list, float4 row loads, closed-form scan.
// ---------------------------------------------------------------------------
__global__ void __launch_bounds__(256)
triplet_kernel(const int* __restrict__ classes, float* __restrict__ out) {
    __shared__ float  drow[N];
    __shared__ int    cls[N];
    __shared__ short  poslist[N];
    __shared__ int    npos;
    __shared__ double warpsum[NWARP];
    __shared__ bool   islast;

    const int i    = blockIdx.x;
    const int tid  = threadIdx.x;     // 256 threads, 8 warps
    const int warp = tid >> 5;
    const int lane = tid & 31;
    if (tid == 0) npos = 0;

    {
        const float4* row = reinterpret_cast<const float4*>(g_dist + i * N);
        for (int q = tid; q < N / 4; q += 256)
            reinterpret_cast<float4*>(drow)[q] = row[q];
        for (int j = tid; j < N; j += 256)
            cls[j] = classes[j];
    }
    __syncthreads();

    // ballot-compacted positive list
    const int ci = cls[i];
    for (int j0 = 0; j0 < N; j0 += 256) {
        const int j = j0 + tid;
        bool flag = (j < N) && (cls[j] == ci) && (j != i);
        unsigned m = __ballot_sync(0xffffffffu, flag);
        int wbase = 0;
        if (lane == 0 && m) wbase = atomicAdd(&npos, __popc(m));
        wbase = __shfl_sync(0xffffffffu, wbase, 0);
        if (flag) {
            int off = __popc(m & ((1u << lane) - 1u));
            poslist[wbase + off] = (short)j;
        }
    }
    __syncthreads();

    const int np = npos;
    if (tid == 0 && np > 0) atomicAdd(&g_den, np);

    double wsum = 0.0;
    for (int p = warp; p < np; p += NWARP) {
        const float t = drow[poslist[p]];     // d(i, j)
        float minw = CUDART_INF_F;            // min x in [0, MARGIN), valid k
        float maxn = -CUDART_INF_F;           // max x < 0, valid k
#pragma unroll
        for (int kk = 0; kk < N / 32; kk++) {
            const int k = kk * 32 + lane;
            float x = drow[k] - t;            // d(i,k) - d(i,j)
            bool valid = (cls[k] != ci);
            minw = fminf(minw, (valid && x >= 0.0f && x < MARGIN) ? x : CUDART_INF_F);
            maxn = fmaxf(maxn, (valid && x < 0.0f) ? x : -CUDART_INF_F);
        }
#pragma unroll
        for (int off = 16; off; off >>= 1) {
            minw = fminf(minw, __shfl_xor_sync(0xffffffffu, minw, off));
            maxn = fmaxf(maxn, __shfl_xor_sync(0xffffffffu, maxn, off));
        }
        float semimax = (minw < CUDART_INF_F) ? (MARGIN - minw) : 0.0f;
        float minhard = MARGIN - maxn;        // +INF if no hard negative
        float pph = (minhard < RHO) ? minhard : 0.0f;
        wsum += (double)((semimax > 0.0f) ? semimax : pph);
    }

    if (lane == 0) warpsum[warp] = wsum;
    __syncthreads();

    if (tid == 0) {
        double s = 0.0;
#pragma unroll
        for (int w = 0; w < NWARP; w++) s += warpsum[w];
        if (s != 0.0) atomicAdd(&g_num, s);
        __threadfence();
        int c = atomicAdd(&g_count, 1);
        islast = (c == NBLK_T - 1);
    }
    __syncthreads();

    if (islast && tid == 0) {
        double num = *(volatile double*)&g_num;   // ordered by fence+counter
        int    den = *(volatile int*)&g_den;
        double r = (den > 0) ? (num / fmax((double)den, 1.0)) : 0.0;
        out[0] = (float)r;
        g_num = 0.0;
        g_den = 0;
        __threadfence();
        g_count = 0;
    }
}

// ---------------------------------------------------------------------------
extern "C" void kernel_launch(void* const* d_in, const int* in_sizes, int n_in,
                              void* d_out, int out_size) {
    const int*   classes = (const int*)d_in[0];
    const float* emb     = (const float*)d_in[1];

    dim3 grid(N / 32, N / 32);        // 144 blocks, one wave
    dist_kernel<<<grid, 256>>>(emb);
    triplet_kernel<<<NBLK_T, 256>>>(classes, (float*)d_out);
}

// round 15
// speedup vs baseline: 1.0171x; 1.0171x over previous
#include <cuda_runtime.h>
#include <math_constants.h>

#define N 384
#define D 128
#define MARGIN 0.2f
#define RHO 10.0f
#define NBLK_B N            // triplet blocks

__device__ float  g_dist[N * N];
__device__ double g_num;
__device__ int    g_den;
__device__ int    g_count;   // zero-init; last block resets each run

// ---------------------------------------------------------------------------
// Kernel A: pairwise squared distances, tiled 32x32 Gram, norms from smem.
// grid (12,12), 256 threads.
// ---------------------------------------------------------------------------
__global__ void __launch_bounds__(256)
dist_kernel(const float* __restrict__ emb) {
    __shared__ float As[32][D];       // anchor rows (row-major, broadcast reads)
    __shared__ float Bs[D][33];       // transposed + padded
    __shared__ float sqA[32], sqB[32];

    const int bi = blockIdx.y * 32;
    const int bj = blockIdx.x * 32;
    const int tid = threadIdx.x;

    for (int idx = tid; idx < 32 * D; idx += 256) {
        int r = idx >> 7;
        int c = idx & (D - 1);
        As[r][c] = emb[(bi + r) * D + c];
        Bs[c][r] = emb[(bj + r) * D + c];
    }
    __syncthreads();

    // local squared norms (threads 0..63)
    if (tid < 32) {
        float s = 0.f;
#pragma unroll
        for (int d = 0; d < D; d++) s = fmaf(As[tid][d], As[tid][d], s);
        sqA[tid] = s;
    } else if (tid < 64) {
        const int r = tid - 32;
        float s = 0.f;
#pragma unroll
        for (int d = 0; d < D; d++) s = fmaf(Bs[d][r], Bs[d][r], s);
        sqB[r] = s;
    }
    __syncthreads();

    const int c  = tid & 31;
    const int r0 = tid >> 5;          // 0..7
    float acc[4] = {0.f, 0.f, 0.f, 0.f};
    for (int d = 0; d < D; d++) {
        float b = Bs[d][c];
#pragma unroll
        for (int q = 0; q < 4; q++)
            acc[q] = fmaf(As[r0 + 8 * q][d], b, acc[q]);
    }
#pragma unroll
    for (int q = 0; q < 4; q++) {
        const int r = r0 + 8 * q;
        float dist = sqA[r] + sqB[c] - 2.0f * acc[q];
        g_dist[(bi + r) * N + (bj + c)] = fmaxf(dist, 0.0f);
    }
}

// ---------------------------------------------------------------------------
// Kernel B: per-anchor triplet reduction (one block per anchor) + finalize.
// ---------------------------------------------------------------------------
__global__ void __launch_bounds__(256)
triplet_kernel(const int* __restrict__ classes, float* __restrict__ out) {
    __shared__ float  drow[N];
    __shared__ int    cls[N];
    __shared__ short  poslist[N];
    __shared__ int    npos;
    __shared__ double warpsum[8];
    __shared__ bool   islast;

    const int i   = blockIdx.x;
    const int tid = threadIdx.x;      // 256 threads, 8 warps
    if (tid == 0) npos = 0;

    for (int j = tid; j < N; j += 256) {
        drow[j] = g_dist[i * N + j];
        cls[j]  = classes[j];
    }
    __syncthreads();

    const int ci = cls[i];
    for (int j = tid; j < N; j += 256) {
        if (cls[j] == ci && j != i) {
            int p = atomicAdd(&npos, 1);
            poslist[p] = (short)j;
        }
    }
    __syncthreads();

    const int np = npos;
    if (tid == 0 && np > 0) atomicAdd(&g_den, np);

    const int warp = tid >> 5;
    const int lane = tid & 31;
    double wsum = 0.0;

    for (int p = warp; p < np; p += 8) {
        const float dij = drow[poslist[p]];
        float semimax = 0.0f;
        float shmin   = CUDART_INF_F;
#pragma unroll
        for (int kk = 0; kk < N / 32; kk++) {
            const int k = kk * 32 + lane;
            float loss  = fmaxf(MARGIN - (drow[k] - dij), 0.0f);
            bool  valid = (cls[k] != ci);
            if (valid && loss > 0.0f && loss <= MARGIN)
                semimax = fmaxf(semimax, loss);
            float sh = loss - ((valid && loss > MARGIN) ? RHO : 0.0f);
            shmin = fminf(shmin, sh);
        }
#pragma unroll
        for (int off = 16; off; off >>= 1) {
            semimax = fmaxf(semimax, __shfl_xor_sync(0xffffffffu, semimax, off));
            shmin   = fminf(shmin,   __shfl_xor_sync(0xffffffffu, shmin,   off));
        }
        float pph = (shmin < 0.0f) ? (shmin + RHO) : 0.0f;
        float ppl = semimax + ((semimax == 0.0f) ? pph : 0.0f);
        wsum += (double)ppl;          // lane-identical after reduction
    }

    if (lane == 0) warpsum[warp] = wsum;
    __syncthreads();

    if (tid == 0) {
        double s = 0.0;
#pragma unroll
        for (int w = 0; w < 8; w++) s += warpsum[w];
        if (s != 0.0) atomicAdd(&g_num, s);
        __threadfence();
        int t = atomicAdd(&g_count, 1);
        islast = (t == NBLK_B - 1);
    }
    __syncthreads();

    if (islast && tid == 0) {
        double num = atomicAdd(&g_num, 0.0);   // fenced read
        int    den = atomicAdd(&g_den, 0);
        double r = (den > 0) ? (num / fmax((double)den, 1.0)) : 0.0;
        out[0] = (float)r;
        g_num = 0.0;
        g_den = 0;
        __threadfence();
        g_count = 0;
    }
}

// ---------------------------------------------------------------------------
extern "C" void kernel_launch(void* const* d_in, const int* in_sizes, int n_in,
                              void* d_out, int out_size) {
    const int*   classes = (const int*)d_in[0];
    const float* emb     = (const float*)d_in[1];

    dim3 grid(N / 32, N / 32);        // 12 x 12 = 144 blocks
    dist_kernel<<<grid, 256>>>(emb);
    triplet_kernel<<<NBLK_B, 256>>>(classes, (float*)d_out);
}